// round 14
// baseline (speedup 1.0000x reference)
#include <cuda_runtime.h>
#include <cuda_fp16.h>
#include <cstdint>
#include <cstddef>
typedef unsigned long long u64;
typedef uint32_t u32;

__device__ __align__(256) float g_app[16384*512];
__device__ __align__(256) float g_motproj[1024*512];
__device__ __align__(256) float g_qproj[128*512];
__device__ __align__(256) float g_objs2[1024*14*512];
__device__ __align__(256) float g_clip[1024*12*512];
__device__ __align__(256) float g_gatesx[1024*2048];
__device__ __align__(256) float g_gates[128*2048];
__device__ __align__(256) float g_hstate[128*512];
__device__ __align__(256) float g_cstate[128*512];
__device__ __align__(256) float g_vm[128*512];
__device__ __align__(256) float g_objs4[128*6*12*512];
__device__ __align__(256) float g_condz[32*128*512];
__device__ __align__(256) float g_zb[2048];
__device__ __align__(256) float g_bsum[2048];
__device__ __align__(256) __half a_catH[14336*1024];

struct MaskArgs { unsigned m[14]; float inv[14]; };

static __device__ __forceinline__ u32 sm_u32(const void* p){
    u32 a; asm("{ .reg .u64 t; cvta.to.shared.u64 t, %1; cvt.u32.u64 %0, t; }":"=r"(a):"l"(p)); return a;
}
#define SW128(o) ((o) ^ (((o) >> 3) & 0x70))
static __device__ __forceinline__ void cpa(u32 s, const void* g){
    asm volatile("cp.async.cg.shared.global [%0], [%1], 16;" :: "r"(s), "l"(g) : "memory");
}
static __device__ __forceinline__ void ldm4(u32* r, u32 a){
    asm volatile("ldmatrix.sync.aligned.m8n8.x4.shared.b16 {%0,%1,%2,%3}, [%4];"
        : "=r"(r[0]),"=r"(r[1]),"=r"(r[2]),"=r"(r[3]) : "r"(a));
}
static __device__ __forceinline__ void mma_f16(float* d, const u32* a, const u32* b){
    asm volatile("mma.sync.aligned.m16n8k16.row.col.f32.f16.f16.f32 "
        "{%0,%1,%2,%3}, {%4,%5,%6,%7}, {%8,%9}, {%0,%1,%2,%3};"
        : "+f"(d[0]),"+f"(d[1]),"+f"(d[2]),"+f"(d[3])
        : "r"(a[0]),"r"(a[1]),"r"(a[2]),"r"(a[3]), "r"(b[0]),"r"(b[1]));
}
static __device__ __forceinline__ uint2 pack_h16(const float* a){
    __half2 p0=__halves2half2(__float2half_rn(a[0]),__float2half_rn(a[1]));
    __half2 p1=__halves2half2(__float2half_rn(a[2]),__float2half_rn(a[3]));
    uint2 o; o.x=*(u32*)&p0; o.y=*(u32*)&p1; return o;
}
// load 128x64 fp32 tile slice into packed-fp16 regs (8 float4 per thread)
static __device__ __forceinline__ void ld32_tile(uint2* st, const float* src, int r0,
                                                 long long ld, int k0, int tid){
#pragma unroll
    for(int i=0;i<8;i++){
        int q=tid+i*256, row=q>>4, f4=q&15;
        float4 v=*(const float4*)(src+(size_t)(r0+row)*ld+k0+f4*4);
        float a[4]={v.x,v.y,v.z,v.w};
        st[i]=pack_h16(a);
    }
}
static __device__ __forceinline__ void sts_tile(const uint2* st, char* sm, u32 off, int tid){
#pragma unroll
    for(int i=0;i<8;i++){
        int q=tid+i*256, row=q>>4, f4=q&15;
        u32 so=SW128((u32)(row*128+(f4>>1)*16))+(f4&1)*8;
        *(uint2*)(sm+off+so)=st[i];
    }
}

// ---- tensor GEMM, fused fp32->fp16 operand conversion ----
// A: fp16 (cp.async) if !A32, else fp32 (LDG+cvt). W always fp32 (LDG+cvt).
template<bool A32>
__global__ void __launch_bounds__(256,2)
tgemm(const void* __restrict__ Av, long long A_step, int lda,
      const float* __restrict__ W, const float* __restrict__ Wb, int wsplit,
      long long W_step, int ldw,
      const float* __restrict__ bias, const float* __restrict__ biasb, long long bias_step,
      const float* __restrict__ addc, long long addc_step, int add_div,
      float* __restrict__ C, long long C_step,
      int c_inner, long long c_so, long long c_sr, int K, int act)
{
    extern __shared__ char dsm[];
    const int tid=threadIdx.x, wid=tid>>5, lane=tid&31;
    const int wm=wid>>2, wn=wid&3;
    const int bm=blockIdx.y*128, bn=blockIdx.x*128, step=blockIdx.z;
    const __half* A16p=(const __half*)Av;
    const float*  A32p=(const float*)Av;
    if(A32) A32p+=(size_t)step*A_step; else A16p+=(size_t)step*A_step;
    const float* Wp; const float* bp;
    if(step>=wsplit){ Wp=Wb+(size_t)(step-wsplit)*W_step; bp=biasb+(size_t)(step-wsplit)*bias_step; }
    else            { Wp=W +(size_t)step*W_step;          bp=bias +(size_t)step*bias_step; }
    if(addc) addc+=(size_t)step*addc_step;
    C+=(size_t)step*C_step;
    u32 raw=sm_u32(dsm), pad=((raw+1023u)&~1023u)-raw;
    char* sm=dsm+pad;
    const u32 base=raw+pad;
    const u32 STAGE=32768u;

    float acc[4][4][4];
#pragma unroll
    for(int i=0;i<4;i++)
#pragma unroll
    for(int j=0;j<4;j++)
#pragma unroll
    for(int k=0;k<4;k++) acc[i][j][k]=0.f;

    const int ntiles=K>>6;
    uint2 wst[8], ast[8];
    // prologue: tile 0
    ld32_tile(wst, Wp, bn, ldw, 0, tid);
    if(A32) ld32_tile(ast, A32p, bm, lda, 0, tid);
    else{
#pragma unroll
        for(int i=0;i<4;i++){
            int q=tid+i*256, row=q>>3, c16=q&7;
            u32 so=SW128((u32)(row*128+c16*16));
            cpa(base+so, A16p+(size_t)(bm+row)*lda+c16*8);
        }
        asm volatile("cp.async.commit_group;" ::: "memory");
    }
    sts_tile(wst, sm, 16384u, tid);
    if(A32) sts_tile(ast, sm, 0u, tid);

    for(int t=0;t<ntiles;t++){
        const u32 cur=(t&1)*STAGE, nxt=((t+1)&1)*STAGE;
        if(t+1<ntiles){
            int k0=(t+1)<<6;
            ld32_tile(wst, Wp, bn, ldw, k0, tid);
            if(A32) ld32_tile(ast, A32p, bm, lda, k0, tid);
            else{
#pragma unroll
                for(int i=0;i<4;i++){
                    int q=tid+i*256, row=q>>3, c16=q&7;
                    u32 so=SW128((u32)(row*128+c16*16));
                    cpa(base+nxt+so, A16p+(size_t)(bm+row)*lda+k0+c16*8);
                }
                asm volatile("cp.async.commit_group;" ::: "memory");
            }
        }
        if(!A32){
            if(t+1<ntiles) asm volatile("cp.async.wait_group 1;" ::: "memory");
            else           asm volatile("cp.async.wait_group 0;" ::: "memory");
        }
        __syncthreads();
        if(t+1<ntiles){
            sts_tile(wst, sm, nxt+16384u, tid);
            if(A32) sts_tile(ast, sm, nxt, tid);
        }
        const int sub=lane>>3, l7=lane&7;
        const int arow=(sub&1)*8+l7, akb=(sub>>1)*16;
        const int brow=(sub>>1)*8+l7, bkb=(sub&1)*16;
#pragma unroll
        for(int ks=0;ks<4;ks++){
            u32 br[2][4];
#pragma unroll
            for(int p=0;p<2;p++){
                int row=wn*32+p*16+brow;
                u32 so=SW128((u32)(row*128+ks*32+bkb));
                ldm4(br[p], base+cur+16384u+so);
            }
#pragma unroll
            for(int mt=0;mt<4;mt++){
                int row=wm*64+mt*16+arow;
                u32 so=SW128((u32)(row*128+ks*32+akb));
                u32 ah[4];
                ldm4(ah, base+cur+so);
#pragma unroll
                for(int nt=0;nt<4;nt++){
                    int p=nt>>1, h=(nt&1)*2;
                    mma_f16(acc[mt][nt], ah, &br[p][h]);
                }
            }
        }
        __syncthreads();
    }
#pragma unroll
    for(int mt=0;mt<4;mt++){
        int mrow=bm+wm*64+mt*16+(lane>>2);
#pragma unroll
        for(int hf=0;hf<2;hf++){
            int m=mrow+hf*8;
            size_t crow=(size_t)(m/c_inner)*(size_t)c_so+(size_t)(m%c_inner)*(size_t)c_sr;
            const float* ac=addc?(addc+(size_t)(m/add_div)*512):nullptr;
#pragma unroll
            for(int nt=0;nt<4;nt++){
                int n=bn+wn*32+nt*8+(lane&3)*2;
                float v0=acc[mt][nt][hf*2+0]+bp[n];
                float v1=acc[mt][nt][hf*2+1]+bp[n+1];
                if(ac){ v0+=ac[n]; v1+=ac[n+1]; }
                float* cp0=C+crow+n;
                if(act==0){ cp0[0]=v0; cp0[1]=v1; }
                else if(act==1){
                    cp0[0]=(v0>0.f)?v0:expm1f(v0);
                    cp0[1]=(v1>0.f)?v1:expm1f(v1);
                } else {
                    cp0[0]*=1.f/(1.f+expf(-v0));
                    cp0[1]*=1.f/(1.f+expf(-v1));
                }
            }
        }
    }
}

__global__ void mean_f16(uint2* __restrict__ h,
    const float* __restrict__ objs, int inner, long long sB, long long sR, long long sJ,
    MaskArgs ma, int M){
    int step=blockIdx.y, idx=blockIdx.x*blockDim.x+threadIdx.x;
    int m=idx>>7, d4=(idx&127)<<2;
    if(m>=M) return;
    unsigned mm=ma.m[step]; float inv=ma.inv[step];
    const float* bp=objs+(size_t)(m/inner)*sB+(size_t)(m%inner)*sR+d4;
    float s0=0,s1=0,s2=0,s3=0;
    while(mm){ int j=__ffs((int)mm)-1; mm&=mm-1;
        float4 v=*(const float4*)(bp+(size_t)j*sJ); s0+=v.x;s1+=v.y;s2+=v.z;s3+=v.w; }
    float a[4]={s0*inv,s1*inv,s2*inv,s3*inv};
    h[(((size_t)step*M+m)*512+d4)>>2]=pack_h16(a);
}
__global__ void meancond_f16(uint2* __restrict__ h,
    const float* __restrict__ objs, int inner, long long sB, long long sR, long long sJ,
    const float* __restrict__ cond, int div, MaskArgs ma, int M){
    int step=blockIdx.y, idx=blockIdx.x*blockDim.x+threadIdx.x;
    int m=idx>>8, g=idx&255;
    if(m>=M) return;
    float a[4];
    if(g<128){
        int d4=g<<2;
        unsigned mm=ma.m[step]; float inv=ma.inv[step];
        const float* bp=objs+(size_t)(m/inner)*sB+(size_t)(m%inner)*sR+d4;
        float s0=0,s1=0,s2=0,s3=0;
        while(mm){ int j=__ffs((int)mm)-1; mm&=mm-1;
            float4 v=*(const float4*)(bp+(size_t)j*sJ); s0+=v.x;s1+=v.y;s2+=v.z;s3+=v.w; }
        a[0]=s0*inv;a[1]=s1*inv;a[2]=s2*inv;a[3]=s3*inv;
    } else {
        int d4=(g-128)<<2;
        float4 v=*(const float4*)(cond+(size_t)(m/div)*512+d4);
        a[0]=v.x;a[1]=v.y;a[2]=v.z;a[3]=v.w;
    }
    h[(((size_t)step*M+m)*1024+(size_t)g*4)>>2]=pack_h16(a);
}
__global__ void zero_kernel(float* p, int n){
    int i=blockIdx.x*blockDim.x+threadIdx.x; if(i<n) p[i]=0.f;
}
__global__ void addvec_kernel(const float* a, const float* b, float* o, int n){
    int i=blockIdx.x*blockDim.x+threadIdx.x; if(i<n) o[i]=a[i]+b[i];
}
__global__ void lstm_cell_kernel(const float* __restrict__ g, long long gsr,
                                 float* __restrict__ h, float* __restrict__ c, int first){
    int idx=blockIdx.x*blockDim.x+threadIdx.x;
    int m=idx>>9, d=idx&511;
    const float* gr=g+(size_t)m*gsr;
    float ig=1.f/(1.f+expf(-gr[d])), fg=1.f/(1.f+expf(-gr[512+d]));
    float gg=tanhf(gr[1024+d]), og=1.f/(1.f+expf(-gr[1536+d]));
    float cold=first?0.f:c[idx];
    float cn=fg*cold+ig*gg;
    c[idx]=cn; h[idx]=og*tanhf(cn);
}
__global__ void __launch_bounds__(256)
sgemm_small(const float* __restrict__ A, int lda, const float* __restrict__ W,
            const float* __restrict__ bias, const float* __restrict__ add, long long add_sr,
            float* __restrict__ C, long long c_sr, int K, int act)
{
    constexpr int BM=64, BK=16;
    __shared__ __align__(16) float As[BK][BM];
    __shared__ __align__(16) float Bs[BK][BM];
    const int bm=blockIdx.y*BM, bn=blockIdx.x*BM;
    const int tid=threadIdx.x, tx=tid&15, ty=tid>>4;
    u64 acc[4][2];
#pragma unroll
    for(int i=0;i<4;i++){acc[i][0]=0ull;acc[i][1]=0ull;}
    for(int k0=0;k0<K;k0+=BK){
        { int r=tid>>2, c4=(tid&3)<<2;
          float4 va=*(const float4*)(A+(size_t)(bm+r)*lda+k0+c4);
          As[c4+0][r]=va.x;As[c4+1][r]=va.y;As[c4+2][r]=va.z;As[c4+3][r]=va.w;
          float4 vb=*(const float4*)(W+(size_t)(bn+r)*K+k0+c4);
          Bs[c4+0][r]=vb.x;Bs[c4+1][r]=vb.y;Bs[c4+2][r]=vb.z;Bs[c4+3][r]=vb.w; }
        __syncthreads();
#pragma unroll
        for(int kk=0;kk<BK;kk++){
            float4 a0=*(const float4*)(&As[kk][ty*4]);
            float av[4]={a0.x,a0.y,a0.z,a0.w};
            double2 b0=*(const double2*)(&Bs[kk][tx*4]);
            u64 bp[2]={(u64)__double_as_longlong(b0.x),(u64)__double_as_longlong(b0.y)};
#pragma unroll
            for(int i=0;i<4;i++){
                u64 ap; asm("mov.b64 %0, {%1, %1};":"=l"(ap):"r"(__float_as_uint(av[i])));
                asm("fma.rn.f32x2 %0, %1, %2, %0;":"+l"(acc[i][0]):"l"(ap),"l"(bp[0]));
                asm("fma.rn.f32x2 %0, %1, %2, %0;":"+l"(acc[i][1]):"l"(ap),"l"(bp[1]));
            }
        }
        __syncthreads();
    }
#pragma unroll
    for(int i=0;i<4;i++){
        int m=bm+ty*4+i;
#pragma unroll
        for(int j=0;j<4;j++){
            int n=bn+tx*4+j;
            u64 pk=acc[i][j>>1];
            unsigned lv=(j&1)?(unsigned)(pk>>32):(unsigned)pk;
            float v=__uint_as_float(lv)+bias[n];
            if(act==3) v+=add[(size_t)m*add_sr+n];
            C[(size_t)m*c_sr+n]=v;
        }
    }
}

namespace {
struct MT19937 {
    unsigned mt[624]; int pos;
    void seed(unsigned s){ for(int i=0;i<624;i++){mt[i]=s; s=1812433253u*(s^(s>>30))+(unsigned)i+1u;} pos=624; }
    unsigned next(){
        if(pos>=624){ for(int i=0;i<624;i++){
            unsigned y=(mt[i]&0x80000000u)|(mt[(i+1)%624]&0x7fffffffu);
            unsigned v=mt[(i+397)%624]^(y>>1); if(y&1u)v^=0x9908b0dfu; mt[i]=v; } pos=0; }
        unsigned y=mt[pos++];
        y^=y>>11; y^=(y<<7)&0x9d2c5680u; y^=(y<<15)&0xefc60000u; y^=y>>18; return y;
    }
    unsigned interval(unsigned mx){
        if(!mx) return 0;
        unsigned m=mx; m|=m>>1;m|=m>>2;m|=m>>4;m|=m>>8;m|=m>>16;
        unsigned v; do{v=next()&m;}while(v>mx); return v;
    }
};
static int perm_first(MT19937& r,int n){
    static int arr[13000];
    for(int i=0;i<n;i++)arr[i]=i;
    for(int i=n-1;i>0;i--){int j=(int)r.interval((unsigned)i);int t=arr[i];arr[i]=arr[j];arr[j]=t;}
    return arr[0];
}
static unsigned unrank_mask(int n,int k,long long idx,const u64 Bn[17][17]){
    unsigned mask=0;int x=0;
    for(int i=0;i<k;i++) for(int v=x;;v++){
        long long c=(long long)Bn[n-1-v][k-1-i];
        if(idx<c){mask|=1u<<v;x=v+1;break;} idx-=c; }
    return mask;
}
constexpr size_t TG_SMEM = 2*32768 + 1024;
template<bool A32>
static void launch_t(const void* Av,long long A_step,int lda,
                     const float* W,const float* Wb,int wsplit,long long W_step,int ldw,
                     const float* bias,const float* biasb,long long bias_step,
                     const float* addc,long long addc_step,int add_div,
                     float* C,long long C_step,int c_inner,long long c_so,long long c_sr,
                     int M,int N,int K,int steps,int act){
    dim3 g(N/128, M/128, steps);
    tgemm<A32><<<g,256,TG_SMEM>>>(Av,A_step,lda,W,Wb,wsplit,W_step,ldw,bias,biasb,bias_step,
                                  addc,addc_step,add_div,C,C_step,c_inner,c_so,c_sr,K,act);
}
template<typename T> static T* sym(T* s){ void* p; cudaGetSymbolAddress(&p,(const void*)s); return (T*)p; }
}

extern "C" void kernel_launch(void* const* d_in, const int* in_sizes, int n_in,
                              void* d_out, int out_size)
{
    (void)in_sizes;(void)n_in;(void)out_size;
    const float* app=(const float*)d_in[0]; const float* mot=(const float*)d_in[1];
    const float* qe=(const float*)d_in[2];  const float* Wq=(const float*)d_in[3];
    const float* bq=(const float*)d_in[4];  const float* Wm=(const float*)d_in[5];
    const float* bmv=(const float*)d_in[6]; const float* Wa=(const float*)d_in[7];
    const float* ba=(const float*)d_in[8];  const float* Wvm=(const float*)d_in[9];
    const float* bvm=(const float*)d_in[10];const float* Wih=(const float*)d_in[11];
    const float* Whh=(const float*)d_in[12];const float* bih=(const float*)d_in[13];
    const float* bhh=(const float*)d_in[14];const float* W1=(const float*)d_in[15];
    const float* b1=(const float*)d_in[16]; const float* W2=(const float*)d_in[17];
    const float* b2=(const float*)d_in[18]; const float* gW2=(const float*)d_in[19];
    const float* gb2=(const float*)d_in[20];const float* W3=(const float*)d_in[21];
    const float* b3=(const float*)d_in[22]; const float* W4=(const float*)d_in[23];
    const float* b4=(const float*)d_in[24]; const float* gW4=(const float*)d_in[25];
    const float* gb4=(const float*)d_in[26];
    float* outp=(float*)d_out;

    cudaFuncSetAttribute(tgemm<true>,  cudaFuncAttributeMaxDynamicSharedMemorySize, (int)TG_SMEM);
    cudaFuncSetAttribute(tgemm<false>, cudaFuncAttributeMaxDynamicSharedMemorySize, (int)TG_SMEM);

    u64 Bn[17][17]={};
    for(int i=0;i<=16;i++){ Bn[i][0]=1;
        for(int j=1;j<=i;j++) Bn[i][j]=Bn[i-1][j-1]+((j<=i-1)?Bn[i-1][j]:0ull); }
    MaskArgs ma1,ma2,ma3,ma4;
    {
        MT19937 rng; rng.seed(0);
        auto doCall=[&](int n,int steps,MaskArgs& o){
            for(int s=0;s<steps;s++){
                int scale=n-(s+1); int pop=(int)Bn[n][scale];
                int r=perm_first(rng,pop);
                o.m[s]=unrank_mask(n,scale,(long long)r,Bn);
                o.inv[s]=1.0f/(float)scale;
            }
        };
        doCall(16,14,ma1); doCall(14,12,ma2); doCall(8,6,ma3); doCall(6,4,ma4);
    }

    float *p_app=sym(g_app),*p_motproj=sym(g_motproj),*p_qproj=sym(g_qproj),
          *p_objs2=sym(g_objs2),*p_clip=sym(g_clip),*p_gatesx=sym(g_gatesx),
          *p_gates=sym(g_gates),*p_hst=sym(g_hstate),*p_cst=sym(g_cstate),
          *p_vm=sym(g_vm),*p_objs4=sym(g_objs4),*p_cz=sym(g_condz),*p_zb=sym(g_zb),
          *p_bsum=sym(g_bsum);
    __half *catH=sym(a_catH);
    const int BIG=1<<30;

    zero_kernel<<<8,256>>>(p_zb,2048);                                   // 1
    addvec_kernel<<<8,256>>>(bih,bhh,p_bsum,2048);                       // 2
    { dim3 g(8,2); sgemm_small<<<g,256>>>(qe,512,Wq,bq,nullptr,0,p_qproj,512,512,0); } // 3
    // 4: app_proj (A32): A=app fp32, W=Wa fp32
    launch_t<true>(app,0,2048, Wa,Wa,BIG,0,2048, ba,ba,0, nullptr,0,1,
                   p_app,0, 16384,0,512, 16384,512,2048,1,0);
    launch_t<true>(mot,0,2048, Wm,Wm,BIG,0,2048, bmv,bmv,0, nullptr,0,1,
                   p_motproj,0, 1024,0,512, 1024,512,2048,1,0);
    launch_t<true>(mot,0,2048, Wih,Wih,BIG,0,2048, p_bsum,p_bsum,0, nullptr,0,1,
                   p_gatesx,0, 1024,0,2048, 1024,2048,2048,1,0);

    const long long WS=512*1024;
    // merged condz: W2(12)+gW2(12) -> cz[0..23]; A=qproj fp32
    launch_t<true>(p_qproj,0,512, W2+WS+512,gW2+WS+512,12,WS,1024,
                   b2+512,gb2+512,512, nullptr,0,1,
                   p_cz,65536, 128,0,512, 128,512,512,24,0);
    // merged condz: W4(4)+gW4(4) -> cz[24..31]
    launch_t<true>(p_qproj,0,512, W4+WS+512,gW4+WS+512,4,WS,1024,
                   b4+512,gb4+512,512, nullptr,0,1,
                   p_cz+24LL*65536,65536, 128,0,512, 128,512,512,8,0);

    // crn_m: 14 steps, K=1024 (A16 cat)
    meancond_f16<<<dim3(1024,14),256>>>((uint2*)catH,p_app,1024,0,16*512,512,
                                        p_motproj,1,ma1,1024);
    launch_t<false>(catH,1024LL*1024,1024, W1+WS,W1+WS,BIG,WS,1024, b1+512,b1+512,512,
                    nullptr,0,1, p_objs2,512, 1024,0,14*512, 1024,512,1024,14,1);
    // crn_q: K=512 mains + condz epilogue
    mean_f16<<<dim3(512,12),256>>>((uint2*)catH,p_objs2,1024,0,14*512,512,ma2,1024);
    launch_t<false>(catH,1024LL*512,512, W2+WS,W2+WS,BIG,WS,1024, p_zb,p_zb,0,
                    p_cz,65536,8, p_clip,512, 1024,0,12*512, 1024,512,512,12,1);
    launch_t<false>(catH,1024LL*512,512, gW2+WS,gW2+WS,BIG,WS,1024, p_zb,p_zb,0,
                    p_cz+12LL*65536,65536,8, p_clip,512, 1024,0,12*512, 1024,512,512,12,2);
    // LSTM (bhh folded into gatesx bias; step0 gemm skipped)
    lstm_cell_kernel<<<256,256>>>(p_gatesx,8*2048,p_hst,p_cst,1);
    for(int t=1;t<8;t++){
        dim3 g(32,2);
        sgemm_small<<<g,256>>>(p_hst,512,Whh,p_zb,p_gatesx+(size_t)t*2048,8*2048,p_gates,2048,512,3);
        lstm_cell_kernel<<<256,256>>>(p_gates,2048,p_hst,p_cst,0);
    }
    { dim3 g(8,2); sgemm_small<<<g,256>>>(p_hst,512,Wvm,bvm,nullptr,0,p_vm,512,512,0); }
    // condz W3 (A=vm fp32) -> cz[0..5]
    launch_t<true>(p_vm,0,512, W3+WS+512,W3+WS+512,BIG,WS,1024, b3+512,b3+512,512,
                   nullptr,0,1, p_cz,65536, 128,0,512, 128,512,512,6,0);
    // crn_vm
    mean_f16<<<dim3(768,6),256>>>((uint2*)catH,p_clip,12,8*12*512,512,12*512,ma3,1536);
    launch_t<false>(catH,1536LL*512,512, W3+WS,W3+WS,BIG,WS,1024, p_zb,p_zb,0,
                    p_cz,65536,12, p_objs4,12*512, 12,6*12*512,512, 1536,512,512,6,1);
    // crn_vq -> out
    mean_f16<<<dim3(768,4),256>>>((uint2*)catH,p_objs4,12,6*12*512,512,12*512,ma4,1536);
    launch_t<false>(catH,1536LL*512,512, W4+WS,W4+WS,BIG,WS,1024, p_zb,p_zb,0,
                    p_cz+24LL*65536,65536,12, outp,12*512, 12,48*512,512, 1536,512,512,4,1);
    launch_t<false>(catH,1536LL*512,512, gW4+WS,gW4+WS,BIG,WS,1024, p_zb,p_zb,0,
                    p_cz+28LL*65536,65536,12, outp,12*512, 12,48*512,512, 1536,512,512,4,2);
}

// round 15
// speedup vs baseline: 1.6048x; 1.6048x over previous
#include <cuda_runtime.h>
#include <cuda_fp16.h>
#include <cstdint>
#include <cstddef>
typedef unsigned long long u64;
typedef uint32_t u32;

__device__ __align__(256) float g_app[16384*512];
__device__ __align__(256) float g_motproj[1024*512];
__device__ __align__(256) float g_qproj[128*512];
__device__ __align__(256) float g_objs2[1024*14*512];
__device__ __align__(256) float g_clip[1024*12*512];
__device__ __align__(256) float g_gatesx[1024*2048];
__device__ __align__(256) float g_gates[128*2048];
__device__ __align__(256) float g_hstate[128*512];
__device__ __align__(256) float g_cstate[128*512];
__device__ __align__(256) float g_vm[128*512];
__device__ __align__(256) float g_objs4[128*6*12*512];
__device__ __align__(256) float g_condz[32*128*512];
__device__ __align__(256) float g_zb[2048];
__device__ __align__(256) float g_bsum[2048];
__device__ __align__(256) __half a_appH[16384*2048];
__device__ __align__(256) __half a_motH[1024*2048];
__device__ __align__(256) __half a_catH[14336*1024];
__device__ __align__(256) __half a_qprH[128*512];
__device__ __align__(256) __half a_vmH[128*512];
__device__ __align__(256) __half a_hH[128*512];
__device__ __align__(256) __half w_Wa[512*2048];
__device__ __align__(256) __half w_Wm[512*2048];
__device__ __align__(256) __half w_Wih[2048*2048];
__device__ __align__(256) __half w_Whh[2048*512];
__device__ __align__(256) __half w_W1[15*512*1024];
__device__ __align__(256) __half w_W2[13*512*1024];
__device__ __align__(256) __half w_gW2[13*512*1024];
__device__ __align__(256) __half w_W3[7*512*1024];
__device__ __align__(256) __half w_W4[5*512*1024];
__device__ __align__(256) __half w_gW4[5*512*1024];

struct MaskArgs { unsigned m[14]; float inv[14]; };

static __device__ __forceinline__ u32 sm_u32(const void* p){
    u32 a; asm("{ .reg .u64 t; cvta.to.shared.u64 t, %1; cvt.u32.u64 %0, t; }":"=r"(a):"l"(p)); return a;
}
#define SW128(o) ((o) ^ (((o) >> 3) & 0x70))
static __device__ __forceinline__ void cpa(u32 s, const void* g){
    asm volatile("cp.async.cg.shared.global [%0], [%1], 16;" :: "r"(s), "l"(g) : "memory");
}
static __device__ __forceinline__ void ldm4(u32* r, u32 a){
    asm volatile("ldmatrix.sync.aligned.m8n8.x4.shared.b16 {%0,%1,%2,%3}, [%4];"
        : "=r"(r[0]),"=r"(r[1]),"=r"(r[2]),"=r"(r[3]) : "r"(a));
}
static __device__ __forceinline__ void mma_f16(float* d, const u32* a, const u32* b){
    asm volatile("mma.sync.aligned.m16n8k16.row.col.f32.f16.f16.f32 "
        "{%0,%1,%2,%3}, {%4,%5,%6,%7}, {%8,%9}, {%0,%1,%2,%3};"
        : "+f"(d[0]),"+f"(d[1]),"+f"(d[2]),"+f"(d[3])
        : "r"(a[0]),"r"(a[1]),"r"(a[2]),"r"(a[3]), "r"(b[0]),"r"(b[1]));
}
static __device__ __forceinline__ uint2 pack_h16(const float* a){
    __half2 p0=__halves2half2(__float2half_rn(a[0]),__float2half_rn(a[1]));
    __half2 p1=__halves2half2(__float2half_rn(a[2]),__float2half_rn(a[3]));
    uint2 o; o.x=*(u32*)&p0; o.y=*(u32*)&p1; return o;
}

// ---- tensor GEMM (fp16 x fp16 -> fp32), 3-stage cp.async pipeline ----
__global__ void __launch_bounds__(256,2)
tgemm(const __half* __restrict__ Ah, long long A_step, int lda,
      const __half* __restrict__ W, const __half* __restrict__ Wb, int wsplit,
      long long W_step, int ldw,
      const float* __restrict__ bias, const float* __restrict__ biasb, long long bias_step,
      const float* __restrict__ addc, long long addc_step, int add_div, long long addc_sr,
      float* __restrict__ C, long long C_step,
      int c_inner, long long c_so, long long c_sr, int K, int act)
{
    extern __shared__ char dsm[];
    const int tid=threadIdx.x, wid=tid>>5, lane=tid&31;
    const int wm=wid>>2, wn=wid&3;
    const int bm=blockIdx.y*128, bn=blockIdx.x*128, step=blockIdx.z;
    Ah+=(size_t)step*A_step;
    const __half* Wp; const float* bp;
    if(step>=wsplit){ Wp=Wb+(size_t)(step-wsplit)*W_step; bp=biasb+(size_t)(step-wsplit)*bias_step; }
    else            { Wp=W +(size_t)step*W_step;          bp=bias +(size_t)step*bias_step; }
    if(addc) addc+=(size_t)step*addc_step;
    C+=(size_t)step*C_step;
    u32 raw=sm_u32(dsm), pad=((raw+1023u)&~1023u)-raw;
    const u32 base=raw+pad;
    const u32 STAGE=32768u;

    float acc[4][4][4];
#pragma unroll
    for(int i=0;i<4;i++)
#pragma unroll
    for(int j=0;j<4;j++)
#pragma unroll
    for(int k=0;k<4;k++) acc[i][j][k]=0.f;

    const int ntiles=K>>6;
    // prologue: stages for tiles 0,1
#pragma unroll
    for(int pt=0;pt<2;pt++){
        if(pt<ntiles){
            const u32 stg=base+(u32)pt*STAGE; const int k0=pt<<6;
#pragma unroll
            for(int i=0;i<4;i++){
                int q=tid+i*256, row=q>>3, c16=q&7;
                u32 so=SW128((u32)(row*128+c16*16));
                cpa(stg+so,       Ah+(size_t)(bm+row)*lda+k0+c16*8);
                cpa(stg+16384+so, Wp+(size_t)(bn+row)*ldw+k0+c16*8);
            }
            asm volatile("cp.async.commit_group;" ::: "memory");
        }
    }
    for(int t=0;t<ntiles;t++){
        if(t+2<ntiles){
            const u32 stg=base+(u32)((t+2)%3)*STAGE; const int k0=(t+2)<<6;
#pragma unroll
            for(int i=0;i<4;i++){
                int q=tid+i*256, row=q>>3, c16=q&7;
                u32 so=SW128((u32)(row*128+c16*16));
                cpa(stg+so,       Ah+(size_t)(bm+row)*lda+k0+c16*8);
                cpa(stg+16384+so, Wp+(size_t)(bn+row)*ldw+k0+c16*8);
            }
            asm volatile("cp.async.commit_group;" ::: "memory");
        }
        int rem=ntiles-1-t;
        if(rem>=2)      asm volatile("cp.async.wait_group 2;" ::: "memory");
        else if(rem==1) asm volatile("cp.async.wait_group 1;" ::: "memory");
        else            asm volatile("cp.async.wait_group 0;" ::: "memory");
        __syncthreads();
        const u32 cur=base+(u32)(t%3)*STAGE;
        const int sub=lane>>3, l7=lane&7;
        const int arow=(sub&1)*8+l7, akb=(sub>>1)*16;
        const int brow=(sub>>1)*8+l7, bkb=(sub&1)*16;
#pragma unroll
        for(int ks=0;ks<4;ks++){
            u32 br[2][4];
#pragma unroll
            for(int p=0;p<2;p++){
                int row=wn*32+p*16+brow;
                u32 so=SW128((u32)(row*128+ks*32+bkb));
                ldm4(br[p], cur+16384u+so);
            }
#pragma unroll
            for(int mt=0;mt<4;mt++){
                int row=wm*64+mt*16+arow;
                u32 so=SW128((u32)(row*128+ks*32+akb));
                u32 ah[4];
                ldm4(ah, cur+so);
#pragma unroll
                for(int nt=0;nt<4;nt++){
                    int p=nt>>1, h=(nt&1)*2;
                    mma_f16(acc[mt][nt], ah, &br[p][h]);
                }
            }
        }
        __syncthreads();
    }
#pragma unroll
    for(int mt=0;mt<4;mt++){
        int mrow=bm+wm*64+mt*16+(lane>>2);
#pragma unroll
        for(int hf=0;hf<2;hf++){
            int m=mrow+hf*8;
            size_t crow=(size_t)(m/c_inner)*(size_t)c_so+(size_t)(m%c_inner)*(size_t)c_sr;
            const float* ac=addc?(addc+(size_t)(m/add_div)*addc_sr):nullptr;
#pragma unroll
            for(int nt=0;nt<4;nt++){
                int n=bn+wn*32+nt*8+(lane&3)*2;
                float v0=acc[mt][nt][hf*2+0]+bp[n];
                float v1=acc[mt][nt][hf*2+1]+bp[n+1];
                if(ac){ v0+=ac[n]; v1+=ac[n+1]; }
                float* cp0=C+crow+n;
                if(act==0){ cp0[0]=v0; cp0[1]=v1; }
                else if(act==1){
                    cp0[0]=(v0>0.f)?v0:expm1f(v0);
                    cp0[1]=(v1>0.f)?v1:expm1f(v1);
                } else {
                    cp0[0]*=1.f/(1.f+expf(-v0));
                    cp0[1]*=1.f/(1.f+expf(-v1));
                }
            }
        }
    }
}

__global__ void conv_f16(const float4* __restrict__ s, uint2* __restrict__ w, int n4){
    int i=(blockIdx.x*blockDim.x+threadIdx.x)*4;
    if(i>=n4) return;
#pragma unroll
    for(int q=0;q<4;q++){
        float4 v=s[i+q];
        float a[4]={v.x,v.y,v.z,v.w};
        w[i+q]=pack_h16(a);
    }
}
__global__ void mean_f16(uint2* __restrict__ h,
    const float* __restrict__ objs, int inner, long long sB, long long sR, long long sJ,
    MaskArgs ma, int M){
    int step=blockIdx.y, idx=blockIdx.x*blockDim.x+threadIdx.x;
    int m=idx>>7, d4=(idx&127)<<2;
    if(m>=M) return;
    unsigned mm=ma.m[step]; float inv=ma.inv[step];
    const float* bp=objs+(size_t)(m/inner)*sB+(size_t)(m%inner)*sR+d4;
    float s0=0,s1=0,s2=0,s3=0;
    while(mm){ int j=__ffs((int)mm)-1; mm&=mm-1;
        float4 v=*(const float4*)(bp+(size_t)j*sJ); s0+=v.x;s1+=v.y;s2+=v.z;s3+=v.w; }
    float a[4]={s0*inv,s1*inv,s2*inv,s3*inv};
    h[(((size_t)step*M+m)*512+d4)>>2]=pack_h16(a);
}
__global__ void meancond_f16(uint2* __restrict__ h,
    const float* __restrict__ objs, int inner, long long sB, long long sR, long long sJ,
    const float* __restrict__ cond, int div, MaskArgs ma, int M){
    int step=blockIdx.y, idx=blockIdx.x*blockDim.x+threadIdx.x;
    int m=idx>>8, g=idx&255;
    if(m>=M) return;
    float a[4];
    if(g<128){
        int d4=g<<2;
        unsigned mm=ma.m[step]; float inv=ma.inv[step];
        const float* bp=objs+(size_t)(m/inner)*sB+(size_t)(m%inner)*sR+d4;
        float s0=0,s1=0,s2=0,s3=0;
        while(mm){ int j=__ffs((int)mm)-1; mm&=mm-1;
            float4 v=*(const float4*)(bp+(size_t)j*sJ); s0+=v.x;s1+=v.y;s2+=v.z;s3+=v.w; }
        a[0]=s0*inv;a[1]=s1*inv;a[2]=s2*inv;a[3]=s3*inv;
    } else {
        int d4=(g-128)<<2;
        float4 v=*(const float4*)(cond+(size_t)(m/div)*512+d4);
        a[0]=v.x;a[1]=v.y;a[2]=v.z;a[3]=v.w;
    }
    h[(((size_t)step*M+m)*1024+(size_t)g*4)>>2]=pack_h16(a);
}
__global__ void zero_kernel(float* p, int n){
    int i=blockIdx.x*blockDim.x+threadIdx.x; if(i<n) p[i]=0.f;
}
__global__ void addvec_kernel(const float* a, const float* b, float* o, int n){
    int i=blockIdx.x*blockDim.x+threadIdx.x; if(i<n) o[i]=a[i]+b[i];
}
// LSTM cell; writes fp32 h, fp16 h (for tensor recurrent GEMM), fp32 c
__global__ void lstm_cell_kernel(const float* __restrict__ g, long long gsr,
                                 float* __restrict__ h, __half* __restrict__ hh,
                                 float* __restrict__ c, int first){
    int idx=blockIdx.x*blockDim.x+threadIdx.x;
    int m=idx>>9, d=idx&511;
    const float* gr=g+(size_t)m*gsr;
    float ig=1.f/(1.f+expf(-gr[d])), fg=1.f/(1.f+expf(-gr[512+d]));
    float gg=tanhf(gr[1024+d]), og=1.f/(1.f+expf(-gr[1536+d]));
    float cold=first?0.f:c[idx];
    float cn=fg*cold+ig*gg;
    float hv=og*tanhf(cn);
    c[idx]=cn; h[idx]=hv; hh[idx]=__float2half_rn(hv);
}
__global__ void __launch_bounds__(256)
sgemm_small(const float* __restrict__ A, int lda, const float* __restrict__ W,
            const float* __restrict__ bias, const float* __restrict__ add, long long add_sr,
            float* __restrict__ C, long long c_sr, int K, int act)
{
    constexpr int BM=64, BK=16;
    __shared__ __align__(16) float As[BK][BM];
    __shared__ __align__(16) float Bs[BK][BM];
    const int bm=blockIdx.y*BM, bn=blockIdx.x*BM;
    const int tid=threadIdx.x, tx=tid&15, ty=tid>>4;
    u64 acc[4][2];
#pragma unroll
    for(int i=0;i<4;i++){acc[i][0]=0ull;acc[i][1]=0ull;}
    for(int k0=0;k0<K;k0+=BK){
        { int r=tid>>2, c4=(tid&3)<<2;
          float4 va=*(const float4*)(A+(size_t)(bm+r)*lda+k0+c4);
          As[c4+0][r]=va.x;As[c4+1][r]=va.y;As[c4+2][r]=va.z;As[c4+3][r]=va.w;
          float4 vb=*(const float4*)(W+(size_t)(bn+r)*K+k0+c4);
          Bs[c4+0][r]=vb.x;Bs[c4+1][r]=vb.y;Bs[c4+2][r]=vb.z;Bs[c4+3][r]=vb.w; }
        __syncthreads();
#pragma unroll
        for(int kk=0;kk<BK;kk++){
            float4 a0=*(const float4*)(&As[kk][ty*4]);
            float av[4]={a0.x,a0.y,a0.z,a0.w};
            double2 b0=*(const double2*)(&Bs[kk][tx*4]);
            u64 bp[2]={(u64)__double_as_longlong(b0.x),(u64)__double_as_longlong(b0.y)};
#pragma unroll
            for(int i=0;i<4;i++){
                u64 ap; asm("mov.b64 %0, {%1, %1};":"=l"(ap):"r"(__float_as_uint(av[i])));
                asm("fma.rn.f32x2 %0, %1, %2, %0;":"+l"(acc[i][0]):"l"(ap),"l"(bp[0]));
                asm("fma.rn.f32x2 %0, %1, %2, %0;":"+l"(acc[i][1]):"l"(ap),"l"(bp[1]));
            }
        }
        __syncthreads();
    }
#pragma unroll
    for(int i=0;i<4;i++){
        int m=bm+ty*4+i;
#pragma unroll
        for(int j=0;j<4;j++){
            int n=bn+tx*4+j;
            u64 pk=acc[i][j>>1];
            unsigned lv=(j&1)?(unsigned)(pk>>32):(unsigned)pk;
            float v=__uint_as_float(lv)+bias[n];
            if(act==3) v+=add[(size_t)m*add_sr+n];
            C[(size_t)m*c_sr+n]=v;
        }
    }
}

namespace {
struct MT19937 {
    unsigned mt[624]; int pos;
    void seed(unsigned s){ for(int i=0;i<624;i++){mt[i]=s; s=1812433253u*(s^(s>>30))+(unsigned)i+1u;} pos=624; }
    unsigned next(){
        if(pos>=624){ for(int i=0;i<624;i++){
            unsigned y=(mt[i]&0x80000000u)|(mt[(i+1)%624]&0x7fffffffu);
            unsigned v=mt[(i+397)%624]^(y>>1); if(y&1u)v^=0x9908b0dfu; mt[i]=v; } pos=0; }
        unsigned y=mt[pos++];
        y^=y>>11; y^=(y<<7)&0x9d2c5680u; y^=(y<<15)&0xefc60000u; y^=y>>18; return y;
    }
    unsigned interval(unsigned mx){
        if(!mx) return 0;
        unsigned m=mx; m|=m>>1;m|=m>>2;m|=m>>4;m|=m>>8;m|=m>>16;
        unsigned v; do{v=next()&m;}while(v>mx); return v;
    }
};
static int perm_first(MT19937& r,int n){
    static int arr[13000];
    for(int i=0;i<n;i++)arr[i]=i;
    for(int i=n-1;i>0;i--){int j=(int)r.interval((unsigned)i);int t=arr[i];arr[i]=arr[j];arr[j]=t;}
    return arr[0];
}
static unsigned unrank_mask(int n,int k,long long idx,const u64 Bn[17][17]){
    unsigned mask=0;int x=0;
    for(int i=0;i<k;i++) for(int v=x;;v++){
        long long c=(long long)Bn[n-1-v][k-1-i];
        if(idx<c){mask|=1u<<v;x=v+1;break;} idx-=c; }
    return mask;
}
constexpr size_t TG_SMEM = 3*32768 + 1024;
static void launch_t(const __half* Ah,long long A_step,int lda,
                     const __half* W,const __half* Wb,int wsplit,long long W_step,int ldw,
                     const float* bias,const float* biasb,long long bias_step,
                     const float* addc,long long addc_step,int add_div,long long addc_sr,
                     float* C,long long C_step,int c_inner,long long c_so,long long c_sr,
                     int M,int N,int K,int steps,int act){
    dim3 g(N/128, M/128, steps);
    tgemm<<<g,256,TG_SMEM>>>(Ah,A_step,lda,W,Wb,wsplit,W_step,ldw,bias,biasb,bias_step,
                             addc,addc_step,add_div,addc_sr,C,C_step,c_inner,c_so,c_sr,K,act);
}
static void convA(const float* s, __half* w, int n){
    int n4=n/4;
    conv_f16<<<(n4/4+255)/256,256>>>((const float4*)s,(uint2*)w,n4);
}
template<typename T> static T* sym(T* s){ void* p; cudaGetSymbolAddress(&p,(const void*)s); return (T*)p; }
}

extern "C" void kernel_launch(void* const* d_in, const int* in_sizes, int n_in,
                              void* d_out, int out_size)
{
    (void)in_sizes;(void)n_in;(void)out_size;
    const float* app=(const float*)d_in[0]; const float* mot=(const float*)d_in[1];
    const float* qe=(const float*)d_in[2];  const float* Wq=(const float*)d_in[3];
    const float* bq=(const float*)d_in[4];  const float* Wm=(const float*)d_in[5];
    const float* bmv=(const float*)d_in[6]; const float* Wa=(const float*)d_in[7];
    const float* ba=(const float*)d_in[8];  const float* Wvm=(const float*)d_in[9];
    const float* bvm=(const float*)d_in[10];const float* Wih=(const float*)d_in[11];
    const float* Whh=(const float*)d_in[12];const float* bih=(const float*)d_in[13];
    const float* bhh=(const float*)d_in[14];const float* W1=(const float*)d_in[15];
    const float* b1=(const float*)d_in[16]; const float* W2=(const float*)d_in[17];
    const float* b2=(const float*)d_in[18]; const float* gW2=(const float*)d_in[19];
    const float* gb2=(const float*)d_in[20];const float* W3=(const float*)d_in[21];
    const float* b3=(const float*)d_in[22]; const float* W4=(const float*)d_in[23];
    const float* b4=(const float*)d_in[24]; const float* gW4=(const float*)d_in[25];
    const float* gb4=(const float*)d_in[26];
    float* outp=(float*)d_out;

    cudaFuncSetAttribute(tgemm, cudaFuncAttributeMaxDynamicSharedMemorySize, (int)TG_SMEM);

    u64 Bn[17][17]={};
    for(int i=0;i<=16;i++){ Bn[i][0]=1;
        for(int j=1;j<=i;j++) Bn[i][j]=Bn[i-1][j-1]+((j<=i-1)?Bn[i-1][j]:0ull); }
    MaskArgs ma1,ma2,ma3,ma4;
    {
        MT19937 rng; rng.seed(0);
        auto doCall=[&](int n,int steps,MaskArgs& o){
            for(int s=0;s<steps;s++){
                int scale=n-(s+1); int pop=(int)Bn[n][scale];
                int r=perm_first(rng,pop);
                o.m[s]=unrank_mask(n,scale,(long long)r,Bn);
                o.inv[s]=1.0f/(float)scale;
            }
        };
        doCall(16,14,ma1); doCall(14,12,ma2); doCall(8,6,ma3); doCall(6,4,ma4);
    }

    float *p_app=sym(g_app),*p_motproj=sym(g_motproj),*p_qproj=sym(g_qproj),
          *p_objs2=sym(g_objs2),*p_clip=sym(g_clip),*p_gatesx=sym(g_gatesx),
          *p_gates=sym(g_gates),*p_hst=sym(g_hstate),*p_cst=sym(g_cstate),
          *p_vm=sym(g_vm),*p_objs4=sym(g_objs4),*p_cz=sym(g_condz),*p_zb=sym(g_zb),
          *p_bsum=sym(g_bsum);
    __half *appH=sym(a_appH),*motH=sym(a_motH),*catH=sym(a_catH),
           *qprH=sym(a_qprH),*vmH=sym(a_vmH),*hH=sym(a_hH),
           *WaF=sym(w_Wa),*WmF=sym(w_Wm),*WihF=sym(w_Wih),*WhhF=sym(w_Whh),
           *W1F=sym(w_W1),*W2F=sym(w_W2),*gW2F=sym(w_gW2),*W3F=sym(w_W3),
           *W4F=sym(w_W4),*gW4F=sym(w_gW4);
    const int BIG=1<<30;

    convA(app,appH,16384*2048);
    convA(mot,motH,1024*2048);
    convA(Wa,WaF,512*2048);
    launch_t(appH,0,2048, WaF,WaF,BIG,0,2048, ba,ba,0, nullptr,0,1,512,
             p_app,0, 16384,0,512, 16384,512,2048,1,0);
    convA(Wm,WmF,512*2048);
    launch_t(motH,0,2048, WmF,WmF,BIG,0,2048, bmv,bmv,0, nullptr,0,1,512,
             p_motproj,0, 1024,0,512, 1024,512,2048,1,0);
    addvec_kernel<<<8,256>>>(bih,bhh,p_bsum,2048);
    convA(Wih,WihF,2048*2048);
    launch_t(motH,0,2048, WihF,WihF,BIG,0,2048, p_bsum,p_bsum,0, nullptr,0,1,512,
             p_gatesx,0, 1024,0,2048, 1024,2048,2048,1,0);
    convA(Whh,WhhF,2048*512);
    convA(W1,W1F,15*512*1024); convA(W2,W2F,13*512*1024);
    convA(gW2,gW2F,13*512*1024); convA(W3,W3F,7*512*1024);
    convA(W4,W4F,5*512*1024); convA(gW4,gW4F,5*512*1024);
    zero_kernel<<<8,256>>>(p_zb,2048);
    { dim3 g(8,2); sgemm_small<<<g,256>>>(qe,512,Wq,bq,nullptr,0,p_qproj,512,512,0); }
    convA(p_qproj,qprH,128*512);

    const long long WS=512*1024;
    // merged condz: W2(12)+gW2(12) -> cz[0..23]
    launch_t(qprH,0,512, W2F+WS+512,gW2F+WS+512,12,WS,1024,
             b2+512,gb2+512,512, nullptr,0,1,512,
             p_cz,65536, 128,0,512, 128,512,512,24,0);
    // merged condz: W4(4)+gW4(4) -> cz[24..31]
    launch_t(qprH,0,512, W4F+WS+512,gW4F+WS+512,4,WS,1024,
             b4+512,gb4+512,512, nullptr,0,1,512,
             p_cz+24LL*65536,65536, 128,0,512, 128,512,512,8,0);

    // crn_m: 14 steps, K=1024
    meancond_f16<<<dim3(1024,14),256>>>((uint2*)catH,p_app,1024,0,16*512,512,
                                        p_motproj,1,ma1,1024);
    launch_t(catH,1024LL*1024,1024, W1F+WS,W1F+WS,BIG,WS,1024, b1+512,b1+512,512,
             nullptr,0,1,512, p_objs2,512, 1024,0,14*512, 1024,512,1024,14,1);
    // crn_q: K=512 mains + condz epilogue
    mean_f16<<<dim3(512,12),256>>>((uint2*)catH,p_objs2,1024,0,14*512,512,ma2,1024);
    launch_t(catH,1024LL*512,512, W2F+WS,W2F+WS,BIG,WS,1024, p_zb,p_zb,0,
             p_cz,65536,8,512, p_clip,512, 1024,0,12*512, 1024,512,512,12,1);
    launch_t(catH,1024LL*512,512, gW2F+WS,gW2F+WS,BIG,WS,1024, p_zb,p_zb,0,
             p_cz+12LL*65536,65536,8,512, p_clip,512, 1024,0,12*512, 1024,512,512,12,2);
    // LSTM: step0 cell from gatesx; steps 1..7 tensor GEMM + cell
    lstm_cell_kernel<<<256,256>>>(p_gatesx,8*2048,p_hst,hH,p_cst,1);
    for(int t=1;t<8;t++){
        launch_t(hH,0,512, WhhF,WhhF,BIG,0,512, p_zb,p_zb,0,
                 p_gatesx+(size_t)t*2048,0,1,8*2048,
                 p_gates,0, 128,0,2048, 128,2048,512,1,0);
        lstm_cell_kernel<<<256,256>>>(p_gates,2048,p_hst,hH,p_cst,0);
    }
    { dim3 g(8,2); sgemm_small<<<g,256>>>(p_hst,512,Wvm,bvm,nullptr,0,p_vm,512,512,0); }
    convA(p_vm,vmH,128*512);
    // condz W3 (A=vm) -> cz[0..5]
    launch_t(vmH,0,512, W3F+WS+512,W3F+WS+512,BIG,WS,1024, b3+512,b3+512,512,
             nullptr,0,1,512, p_cz,65536, 128,0,512, 128,512,512,6,0);
    // crn_vm
    mean_f16<<<dim3(768,6),256>>>((uint2*)catH,p_clip,12,8*12*512,512,12*512,ma3,1536);
    launch_t(catH,1536LL*512,512, W3F+WS,W3F+WS,BIG,WS,1024, p_zb,p_zb,0,
             p_cz,65536,12,512, p_objs4,12*512, 12,6*12*512,512, 1536,512,512,6,1);
    // crn_vq -> out
    mean_f16<<<dim3(768,4),256>>>((uint2*)catH,p_objs4,12,6*12*512,512,12*512,ma4,1536);
    launch_t(catH,1536LL*512,512, W4F+WS,W4F+WS,BIG,WS,1024, p_zb,p_zb,0,
             p_cz+24LL*65536,65536,12,512, outp,12*512, 12,48*512,512, 1536,512,512,4,1);
    launch_t(catH,1536LL*512,512, gW4F+WS,gW4F+WS,BIG,WS,1024, p_zb,p_zb,0,
             p_cz+28LL*65536,65536,12,512, outp,12*512, 12,48*512,512, 1536,512,512,4,2);
}